// round 5
// baseline (speedup 1.0000x reference)
#include <cuda_runtime.h>
#include <math.h>

#define D 128
#define NMAX 100000
#define EMAX 1600000

// Scratch (static __device__ — no allocations allowed)
__device__ float  g_h [(size_t)NMAX * D];
__device__ float  g_y1[(size_t)NMAX * D];
__device__ float  g_y2[(size_t)NMAX * D];
__device__ double g_acc[6];        // (sum, sumsq) x 3 layernorms
__device__ int    g_deg[NMAX + 1]; // per-dst degree (histogram)
__device__ int    g_off[NMAX + 1]; // CSR offsets
__device__ int    g_cur[NMAX + 1]; // fill cursors
__device__ int    g_csr[EMAX];     // src ids grouped by dst

// ---------------------------------------------------------------------------
// CSR build phase 1: histogram of dst
// ---------------------------------------------------------------------------
__global__ void k_hist(const int* __restrict__ dst, int ne) {
    int i = blockIdx.x * blockDim.x + threadIdx.x;
    int i4 = i * 4;
    if (i4 + 4 <= ne) {
        int4 d = __ldg((const int4*)dst + i);
        atomicAdd(&g_deg[d.x], 1);
        atomicAdd(&g_deg[d.y], 1);
        atomicAdd(&g_deg[d.z], 1);
        atomicAdd(&g_deg[d.w], 1);
    } else {
        for (int e = i4; e < ne; e++) atomicAdd(&g_deg[__ldg(dst + e)], 1);
    }
}

// ---------------------------------------------------------------------------
// CSR build phase 2: exclusive scan (single block, 1024 threads)
// ---------------------------------------------------------------------------
__global__ void k_scan(int n1) {
    __shared__ int sh[1024];
    int t = threadIdx.x;
    int chunk = (n1 + 1023) >> 10;
    int beg = t * chunk, end = min(beg + chunk, n1);
    int s = 0;
    for (int i = beg; i < end; i++) s += g_deg[i];
    sh[t] = s;
    __syncthreads();
    for (int off = 1; off < 1024; off <<= 1) {
        int v = (t >= off) ? sh[t - off] : 0;
        __syncthreads();
        sh[t] += v;
        __syncthreads();
    }
    int run = (t == 0) ? 0 : sh[t - 1];
    for (int i = beg; i < end; i++) {
        g_off[i] = run;
        g_cur[i] = run;
        run += g_deg[i];
    }
}

// ---------------------------------------------------------------------------
// CSR build phase 3: scatter src ids into slots
// ---------------------------------------------------------------------------
__global__ void k_fill(const int* __restrict__ ei, int ne) {
    int e = blockIdx.x * blockDim.x + threadIdx.x;
    if (e >= ne) return;
    int src = __ldg(ei + e);
    int dst = __ldg(ei + ne + e);
    int pos = atomicAdd(&g_cur[dst], 1);
    g_csr[pos] = src;
}

// ---------------------------------------------------------------------------
// Aggregation: one warp per node.  h[i] = (1+eps)*node[i] + sum_{src->i} node[src]
// Atomic-free; gather reads are L2-resident (node = 51MB < 126MB L2).
// ---------------------------------------------------------------------------
__global__ void k_aggr(const float* __restrict__ node, const float* __restrict__ epsp, int n) {
    int w    = (blockIdx.x * blockDim.x + threadIdx.x) >> 5;
    int lane = threadIdx.x & 31;
    if (w >= n) return;
    float s = 1.0f + __ldg(epsp);
    float4 acc = __ldg((const float4*)(node + (size_t)w * D) + lane);
    acc.x *= s; acc.y *= s; acc.z *= s; acc.w *= s;
    int beg = __ldg(&g_off[w]), end = __ldg(&g_off[w + 1]);
    int j = beg;
    for (; j + 4 <= end; j += 4) {   // MLP=4: 4 gathers in flight
        int s0 = __ldg(&g_csr[j]),     s1 = __ldg(&g_csr[j + 1]);
        int s2 = __ldg(&g_csr[j + 2]), s3 = __ldg(&g_csr[j + 3]);
        float4 v0 = __ldg((const float4*)(node + (size_t)s0 * D) + lane);
        float4 v1 = __ldg((const float4*)(node + (size_t)s1 * D) + lane);
        float4 v2 = __ldg((const float4*)(node + (size_t)s2 * D) + lane);
        float4 v3 = __ldg((const float4*)(node + (size_t)s3 * D) + lane);
        acc.x += (v0.x + v1.x) + (v2.x + v3.x);
        acc.y += (v0.y + v1.y) + (v2.y + v3.y);
        acc.z += (v0.z + v1.z) + (v2.z + v3.z);
        acc.w += (v0.w + v1.w) + (v2.w + v3.w);
    }
    for (; j < end; j++) {
        int s0 = __ldg(&g_csr[j]);
        float4 v = __ldg((const float4*)(node + (size_t)s0 * D) + lane);
        acc.x += v.x; acc.y += v.y; acc.z += v.z; acc.w += v.w;
    }
    ((float4*)(g_h + (size_t)w * D))[lane] = acc;
}

// ---------------------------------------------------------------------------
// GEMM: Y[n,128] = transform(A)[n,128] @ W[128,128] + bias
//  - fused input LN+ReLU from previous layer's stats (computed in-block)
//  - fused epilogue sum/sumsq -> double atomics
//  - f32x2 packed FFMA2 inner loop
// ---------------------------------------------------------------------------
__device__ __forceinline__ unsigned long long dupf(float x) {
    unsigned long long r;
    unsigned u = __float_as_uint(x);
    asm("mov.b64 %0, {%1,%1};" : "=l"(r) : "r"(u));
    return r;
}
#define FMA2(acc, a, b) asm("fma.rn.f32x2 %0, %1, %2, %0;" : "+l"(acc) : "l"(a), "l"(b))

template<bool LN>
__global__ void k_gemm(const float* __restrict__ A, const float* __restrict__ W,
                       const float* __restrict__ bias,
                       const float* __restrict__ lnw, const float* __restrict__ lnb,
                       const double* __restrict__ acc_in, double cnt,
                       float* __restrict__ Y, double* __restrict__ acc_out, int n)
{
    extern __shared__ __align__(16) char smem[];
    float* Ws  = (float*)smem;                    // 128*128 floats = 64KB
    float* As  = (float*)(smem + 65536);          // 16*64 floats   = 4KB
    float* red = (float*)(smem + 65536 + 4096);   // 16 floats

    int tid = threadIdx.x;
    int tx = tid & 15, ty = tid >> 4;
    int row0 = blockIdx.x * 64;

    // Stats finalize (fused, replaces separate k_fin launch)
    if constexpr (LN) {
        if (tid == 0) {
            double m = acc_in[0] / cnt;
            double var = acc_in[1] / cnt - m * m;
            if (var < 0.0) var = 0.0;
            red[0] = (float)m;
            red[1] = 1.0f / ((float)sqrt(var) + 1e-5f);
        }
    }

    // Stage full W into smem
    {
        const float4* W4 = (const float4*)W;
        float4* Ws4 = (float4*)Ws;
        #pragma unroll
        for (int i = 0; i < 16; i++) Ws4[tid + 256 * i] = __ldg(W4 + tid + 256 * i);
    }
    __syncthreads();

    float mean = 0.f, inv = 0.f;
    if constexpr (LN) { mean = red[0]; inv = red[1]; }

    int r  = tid >> 2;
    int kg = (tid & 3) * 4;
    int grow_ld = row0 + r;

    auto loadA = [&](int c) -> float4 {
        float4 v = make_float4(0.f, 0.f, 0.f, 0.f);
        if (grow_ld < n) {
            v = __ldg((const float4*)(A + (size_t)grow_ld * D + c * 16 + kg));
            if constexpr (LN) {
                int kb = c * 16 + kg;
                float4 wv = __ldg((const float4*)(lnw + kb));
                float4 bv = __ldg((const float4*)(lnb + kb));
                v.x = fmaxf(fmaf((v.x - mean) * inv, wv.x, bv.x), 0.f);
                v.y = fmaxf(fmaf((v.y - mean) * inv, wv.y, bv.y), 0.f);
                v.z = fmaxf(fmaf((v.z - mean) * inv, wv.z, bv.z), 0.f);
                v.w = fmaxf(fmaf((v.w - mean) * inv, wv.w, bv.w), 0.f);
            }
        }
        return v;
    };

    float4 areg = loadA(0);

    unsigned long long acc[4][4];
    #pragma unroll
    for (int j = 0; j < 4; j++)
        #pragma unroll
        for (int p = 0; p < 4; p++) acc[j][p] = 0ULL;

    for (int c = 0; c < 8; c++) {
        __syncthreads();
        As[(kg + 0) * 64 + r] = areg.x;
        As[(kg + 1) * 64 + r] = areg.y;
        As[(kg + 2) * 64 + r] = areg.z;
        As[(kg + 3) * 64 + r] = areg.w;
        __syncthreads();
        if (c < 7) areg = loadA(c + 1);

        #pragma unroll
        for (int kk = 0; kk < 16; kk++) {
            int k = c * 16 + kk;
            float4 av = *(const float4*)&As[kk * 64 + ty * 4];
            ulonglong2 b0 = *(const ulonglong2*)&Ws[k * 128 + tx * 8];
            ulonglong2 b1 = *(const ulonglong2*)&Ws[k * 128 + tx * 8 + 4];
            unsigned long long a0 = dupf(av.x), a1 = dupf(av.y);
            unsigned long long a2 = dupf(av.z), a3 = dupf(av.w);
            FMA2(acc[0][0], a0, b0.x); FMA2(acc[0][1], a0, b0.y);
            FMA2(acc[0][2], a0, b1.x); FMA2(acc[0][3], a0, b1.y);
            FMA2(acc[1][0], a1, b0.x); FMA2(acc[1][1], a1, b0.y);
            FMA2(acc[1][2], a1, b1.x); FMA2(acc[1][3], a1, b1.y);
            FMA2(acc[2][0], a2, b0.x); FMA2(acc[2][1], a2, b0.y);
            FMA2(acc[2][2], a2, b1.x); FMA2(acc[2][3], a2, b1.y);
            FMA2(acc[3][0], a3, b0.x); FMA2(acc[3][1], a3, b0.y);
            FMA2(acc[3][2], a3, b1.x); FMA2(acc[3][3], a3, b1.y);
        }
    }

    // Epilogue: unpack, add bias, store, accumulate LN stats
    float4 bo0 = __ldg((const float4*)(bias + tx * 8));
    float4 bo1 = __ldg((const float4*)(bias + tx * 8 + 4));
    float lsum = 0.f, lsq = 0.f;
    #pragma unroll
    for (int j = 0; j < 4; j++) {
        int grow = row0 + ty * 4 + j;
        if (grow < n) {
            float o[8];
            #pragma unroll
            for (int p = 0; p < 4; p++) {
                unsigned lo, hi;
                asm("mov.b64 {%0,%1}, %2;" : "=r"(lo), "=r"(hi) : "l"(acc[j][p]));
                o[2 * p]     = __uint_as_float(lo);
                o[2 * p + 1] = __uint_as_float(hi);
            }
            o[0] += bo0.x; o[1] += bo0.y; o[2] += bo0.z; o[3] += bo0.w;
            o[4] += bo1.x; o[5] += bo1.y; o[6] += bo1.z; o[7] += bo1.w;
            float4* yp = (float4*)(Y + (size_t)grow * D + tx * 8);
            yp[0] = make_float4(o[0], o[1], o[2], o[3]);
            yp[1] = make_float4(o[4], o[5], o[6], o[7]);
            #pragma unroll
            for (int q = 0; q < 8; q++) { lsum += o[q]; lsq += o[q] * o[q]; }
        }
    }
    #pragma unroll
    for (int off = 16; off; off >>= 1) {
        lsum += __shfl_xor_sync(0xffffffffu, lsum, off);
        lsq  += __shfl_xor_sync(0xffffffffu, lsq,  off);
    }
    int wid = tid >> 5, lane = tid & 31;
    __syncthreads();
    if (lane == 0) { red[wid] = lsum; red[8 + wid] = lsq; }
    __syncthreads();
    if (tid == 0) {
        float s = 0.f, q = 0.f;
        #pragma unroll
        for (int w = 0; w < 8; w++) { s += red[w]; q += red[8 + w]; }
        atomicAdd(acc_out,     (double)s);
        atomicAdd(acc_out + 1, (double)q);
    }
}

// ---------------------------------------------------------------------------
// Final: out = relu(LN(out)) in place (stats finalized in-block)
// ---------------------------------------------------------------------------
__global__ void k_final(float* __restrict__ y, const float* __restrict__ lnw,
                        const float* __restrict__ lnb, const double* __restrict__ acc_in,
                        double cnt, int n) {
    __shared__ float sm[2];
    if (threadIdx.x == 0) {
        double m = acc_in[0] / cnt;
        double var = acc_in[1] / cnt - m * m;
        if (var < 0.0) var = 0.0;
        sm[0] = (float)m;
        sm[1] = 1.0f / ((float)sqrt(var) + 1e-5f);
    }
    __syncthreads();
    int i = blockIdx.x * blockDim.x + threadIdx.x;
    if (i >= n * (D / 4)) return;
    float mean = sm[0], inv = sm[1];
    float4 v = ((float4*)y)[i];
    int kb = (i * 4) & (D - 1);
    float4 wv = __ldg((const float4*)(lnw + kb));
    float4 bv = __ldg((const float4*)(lnb + kb));
    v.x = fmaxf(fmaf((v.x - mean) * inv, wv.x, bv.x), 0.f);
    v.y = fmaxf(fmaf((v.y - mean) * inv, wv.y, bv.y), 0.f);
    v.z = fmaxf(fmaf((v.z - mean) * inv, wv.z, bv.z), 0.f);
    v.w = fmaxf(fmaf((v.w - mean) * inv, wv.w, bv.w), 0.f);
    ((float4*)y)[i] = v;
}

// ---------------------------------------------------------------------------
extern "C" void kernel_launch(void* const* d_in, const int* in_sizes, int n_in,
                              void* d_out, int out_size) {
    const float* node = (const float*)d_in[0];
    const int*   ei   = (const int*)d_in[1];
    const float* epsp = (const float*)d_in[4];
    const float* W1 = (const float*)d_in[5];  const float* b1 = (const float*)d_in[6];
    const float* l1w = (const float*)d_in[7]; const float* l1b = (const float*)d_in[8];
    const float* W2 = (const float*)d_in[9];  const float* b2 = (const float*)d_in[10];
    const float* l2w = (const float*)d_in[11]; const float* l2b = (const float*)d_in[12];
    const float* W3 = (const float*)d_in[13]; const float* b3 = (const float*)d_in[14];
    const float* low = (const float*)d_in[15]; const float* lob = (const float*)d_in[16];
    float* out = (float*)d_out;

    int n  = in_sizes[0] / D;
    int ne = in_sizes[1] / 2;

    float *hP, *y1P, *y2P; double* accP; int* degP;
    cudaGetSymbolAddress((void**)&hP,  g_h);
    cudaGetSymbolAddress((void**)&y1P, g_y1);
    cudaGetSymbolAddress((void**)&y2P, g_y2);
    cudaGetSymbolAddress((void**)&accP, g_acc);
    cudaGetSymbolAddress((void**)&degP, g_deg);

    const int smem = 65536 + 4096 + 64;
    cudaFuncSetAttribute(k_gemm<false>, cudaFuncAttributeMaxDynamicSharedMemorySize, smem);
    cudaFuncSetAttribute(k_gemm<true>,  cudaFuncAttributeMaxDynamicSharedMemorySize, smem);

    int t4 = n * (D / 4);
    double cnt = (double)n * D;
    int gb = (n + 63) / 64;

    // CSR build (counting sort by dst)
    cudaMemsetAsync(degP, 0, (size_t)(n + 1) * sizeof(int));
    cudaMemsetAsync(accP, 0, 6 * sizeof(double));
    k_hist<<<(ne / 4 + 255) / 256, 256>>>(ei + ne, ne);
    k_scan<<<1, 1024>>>(n + 1);
    k_fill<<<(ne + 255) / 256, 256>>>(ei, ne);

    // Aggregation (atomic-free) + fused (1+eps)*node
    k_aggr<<<(n * 32 + 255) / 256, 256>>>(node, epsp, n);

    // MLP with fused graph-LN stats
    k_gemm<false><<<gb, 256, smem>>>(hP,  W1, b1, nullptr, nullptr, nullptr,  cnt, y1P, accP,     n);
    k_gemm<true ><<<gb, 256, smem>>>(y1P, W2, b2, l1w, l1b, accP,             cnt, y2P, accP + 2, n);
    k_gemm<true ><<<gb, 256, smem>>>(y2P, W3, b3, l2w, l2b, accP + 2,         cnt, out, accP + 4, n);
    k_final<<<(t4 + 255) / 256, 256>>>(out, low, lob, accP + 4, cnt, n);
}

// round 7
// speedup vs baseline: 1.2572x; 1.2572x over previous
#include <cuda_runtime.h>
#include <math.h>

#define D 128
#define NMAX 100000
#define EMAX 1600000

// Scratch (static __device__ — no allocations allowed)
__device__ float  g_h [(size_t)NMAX * D];
__device__ float  g_y1[(size_t)NMAX * D];
__device__ float  g_y2[(size_t)NMAX * D];
__device__ double g_acc[6];        // (sum, sumsq) x 3 layernorms
__device__ int    g_deg[NMAX + 1]; // per-dst degree (histogram)
__device__ int    g_off[NMAX + 1]; // CSR offsets
__device__ int    g_cur[NMAX + 1]; // fill cursors
__device__ int    g_csr[EMAX];     // src ids grouped by dst

// ---------------------------------------------------------------------------
// CSR phase 1: histogram of dst (+ zero the LN stat accumulators)
// ---------------------------------------------------------------------------
__global__ void k_hist(const int* __restrict__ dst, int ne) {
    if (blockIdx.x == 0 && threadIdx.x < 6) g_acc[threadIdx.x] = 0.0;
    int i = blockIdx.x * blockDim.x + threadIdx.x;
    int i4 = i * 4;
    if (i4 + 4 <= ne) {
        int4 d = __ldg((const int4*)dst + i);
        atomicAdd(&g_deg[d.x], 1);
        atomicAdd(&g_deg[d.y], 1);
        atomicAdd(&g_deg[d.z], 1);
        atomicAdd(&g_deg[d.w], 1);
    } else {
        for (int e = i4; e < ne; e++) atomicAdd(&g_deg[__ldg(dst + e)], 1);
    }
}

// ---------------------------------------------------------------------------
// CSR phase 2: exclusive scan (single block, 1024 threads)
// ---------------------------------------------------------------------------
__global__ void k_scan(int n1) {
    __shared__ int sh[1024];
    int t = threadIdx.x;
    int chunk = (n1 + 1023) >> 10;
    int beg = t * chunk, end = min(beg + chunk, n1);
    int s = 0;
    for (int i = beg; i < end; i++) s += __ldg(&g_deg[i]);
    sh[t] = s;
    __syncthreads();
    for (int off = 1; off < 1024; off <<= 1) {
        int v = (t >= off) ? sh[t - off] : 0;
        __syncthreads();
        sh[t] += v;
        __syncthreads();
    }
    int run = (t == 0) ? 0 : sh[t - 1];
    for (int i = beg; i < end; i++) {
        int d = __ldg(&g_deg[i]);
        g_off[i] = run;
        g_cur[i] = run;
        run += d;
    }
}

// ---------------------------------------------------------------------------
// CSR phase 3: scatter src ids into slots (4 edges/thread, vector loads)
// ---------------------------------------------------------------------------
__global__ void k_fill(const int* __restrict__ ei, int ne) {
    int i = blockIdx.x * blockDim.x + threadIdx.x;
    int e4 = i * 4;
    if (e4 + 4 <= ne) {
        int4 s = __ldg((const int4*)(ei) + i);
        int4 d = __ldg((const int4*)(ei + ne) + i);
        g_csr[atomicAdd(&g_cur[d.x], 1)] = s.x;
        g_csr[atomicAdd(&g_cur[d.y], 1)] = s.y;
        g_csr[atomicAdd(&g_cur[d.z], 1)] = s.z;
        g_csr[atomicAdd(&g_cur[d.w], 1)] = s.w;
    } else {
        for (int e = e4; e < ne; e++) {
            int src = __ldg(ei + e);
            int dst = __ldg(ei + ne + e);
            g_csr[atomicAdd(&g_cur[dst], 1)] = src;
        }
    }
}

// ---------------------------------------------------------------------------
// Aggregation: one warp per node. h[i] = (1+eps)*node[i] + sum_{src->i} node[src]
// Atomic-free; MLP=8 gathers in flight (L2-resident node table).
// ---------------------------------------------------------------------------
__global__ void k_aggr(const float* __restrict__ node, const float* __restrict__ epsp, int n) {
    int w    = (blockIdx.x * blockDim.x + threadIdx.x) >> 5;
    int lane = threadIdx.x & 31;
    if (w >= n) return;
    float s = 1.0f + __ldg(epsp);
    float4 acc = __ldg((const float4*)(node + (size_t)w * D) + lane);
    acc.x *= s; acc.y *= s; acc.z *= s; acc.w *= s;
    int beg = __ldg(&g_off[w]), end = __ldg(&g_off[w + 1]);
    int j = beg;
    for (; j + 8 <= end; j += 8) {
        int sx[8];
        #pragma unroll
        for (int q = 0; q < 8; q++) sx[q] = __ldg(&g_csr[j + q]);
        float4 v[8];
        #pragma unroll
        for (int q = 0; q < 8; q++) v[q] = __ldg((const float4*)(node + (size_t)sx[q] * D) + lane);
        #pragma unroll
        for (int q = 0; q < 8; q++) {
            acc.x += v[q].x; acc.y += v[q].y; acc.z += v[q].z; acc.w += v[q].w;
        }
    }
    for (; j < end; j++) {
        int s0 = __ldg(&g_csr[j]);
        float4 v = __ldg((const float4*)(node + (size_t)s0 * D) + lane);
        acc.x += v.x; acc.y += v.y; acc.z += v.z; acc.w += v.w;
    }
    ((float4*)(g_h + (size_t)w * D))[lane] = acc;
}

// ---------------------------------------------------------------------------
// GEMM: Y[n,128] = transform(A)[n,128] @ W[128,128] + bias
// 128x128 block tile, 8x8 thread tile, f32x2 FFMA2, double-buffered A smem.
//  - fused input LN+ReLU (stats finalized in-block from double accumulators)
//  - fused epilogue sum/sumsq -> double atomics
// ---------------------------------------------------------------------------
__device__ __forceinline__ unsigned long long dupf(float x) {
    unsigned long long r;
    unsigned u = __float_as_uint(x);
    asm("mov.b64 %0, {%1,%1};" : "=l"(r) : "r"(u));
    return r;
}
#define FMA2(acc, a, b) asm("fma.rn.f32x2 %0, %1, %2, %0;" : "+l"(acc) : "l"(a), "l"(b))

#define SM_WS   0
#define SM_AS   65536
#define SM_RED  (65536 + 16384)
#define SM_TOT  (65536 + 16384 + 128)

template<bool LN>
__global__ void __launch_bounds__(256, 2)
k_gemm(const float* __restrict__ A, const float* __restrict__ W,
       const float* __restrict__ bias,
       const float* __restrict__ lnw, const float* __restrict__ lnb,
       const double* __restrict__ acc_in, double cnt,
       float* __restrict__ Y, double* __restrict__ acc_out, int n)
{
    extern __shared__ __align__(16) char smem[];
    float* Ws  = (float*)(smem + SM_WS);    // 128x128        = 64KB
    float* As  = (float*)(smem + SM_AS);    // 2 x 16 x 128   = 16KB
    float* red = (float*)(smem + SM_RED);

    int tid = threadIdx.x;
    int tx = tid & 15, ty = tid >> 4;       // 16x16 thread grid, 8x8 tile each
    int row0 = blockIdx.x * 128;

    // Finalize previous layer's LN stats (replaces a separate launch)
    if constexpr (LN) {
        if (tid == 0) {
            double m = acc_in[0] / cnt;
            double var = acc_in[1] / cnt - m * m;
            if (var < 0.0) var = 0.0;
            red[0] = (float)m;
            red[1] = 1.0f / ((float)sqrt(var) + 1e-5f);
        }
    }

    // Stage full W into smem (row-major, 128 floats per k-row)
    {
        const float4* W4 = (const float4*)W;
        float4* Ws4 = (float4*)Ws;
        #pragma unroll
        for (int i = 0; i < 16; i++) Ws4[tid + 256 * i] = __ldg(W4 + tid + 256 * i);
    }
    __syncthreads();

    float mean = 0.f, inv = 0.f;
    if constexpr (LN) { mean = red[0]; inv = red[1]; }

    // A staging: thread loads 8 floats of one row per chunk
    int lrow = tid >> 1;                 // 0..127
    int lk   = (tid & 1) * 8;            // 0 or 8 within 16-wide chunk
    int grow_ld = row0 + lrow;

    float pf[8];
    auto loadA = [&](int c) {
        if (grow_ld < n) {
            float4 v0 = __ldg((const float4*)(A + (size_t)grow_ld * D + c * 16 + lk));
            float4 v1 = __ldg((const float4*)(A + (size_t)grow_ld * D + c * 16 + lk + 4));
            if constexpr (LN) {
                int kb = c * 16 + lk;
                float4 w0 = __ldg((const float4*)(lnw + kb));
                float4 w1 = __ldg((const float4*)(lnw + kb + 4));
                float4 b0 = __ldg((const float4*)(lnb + kb));
                float4 b1 = __ldg((const float4*)(lnb + kb + 4));
                v0.x = fmaxf(fmaf((v0.x - mean) * inv, w0.x, b0.x), 0.f);
                v0.y = fmaxf(fmaf((v0.y - mean) * inv, w0.y, b0.y), 0.f);
                v0.z = fmaxf(fmaf((v0.z - mean) * inv, w0.z, b0.z), 0.f);
                v0.w = fmaxf(fmaf((v0.w - mean) * inv, w0.w, b0.w), 0.f);
                v1.x = fmaxf(fmaf((v1.x - mean) * inv, w1.x, b1.x), 0.f);
                v1.y = fmaxf(fmaf((v1.y - mean) * inv, w1.y, b1.y), 0.f);
                v1.z = fmaxf(fmaf((v1.z - mean) * inv, w1.z, b1.z), 0.f);
                v1.w = fmaxf(fmaf((v1.w - mean) * inv, w1.w, b1.w), 0.f);
            }
            pf[0] = v0.x; pf[1] = v0.y; pf[2] = v0.z; pf[3] = v0.w;
            pf[4] = v1.x; pf[5] = v1.y; pf[6] = v1.z; pf[7] = v1.w;
        } else {
            #pragma unroll
            for (int q = 0; q < 8; q++) pf[q] = 0.f;
        }
    };

    loadA(0);

    unsigned long long acc[8][4];       // 8 rows x 4 col-pairs
    #pragma unroll
    for (int r = 0; r < 8; r++)
        #pragma unroll
        for (int p = 0; p < 4; p++) acc[r][p] = 0ULL;

    for (int c = 0; c < 8; c++) {
        float* Ab = As + (c & 1) * 2048;            // 16*128 floats per buffer
        #pragma unroll
        for (int q = 0; q < 8; q++) Ab[(lk + q) * 128 + lrow] = pf[q];
        __syncthreads();
        if (c < 7) loadA(c + 1);                    // prefetch behind compute

        #pragma unroll
        for (int kk = 0; kk < 16; kk++) {
            int k = c * 16 + kk;
            float4 a0 = *(const float4*)&Ab[kk * 128 + ty * 8];
            float4 a1 = *(const float4*)&Ab[kk * 128 + ty * 8 + 4];
            ulonglong2 w0 = *(const ulonglong2*)&Ws[k * 128 + tx * 8];
            ulonglong2 w1 = *(const ulonglong2*)&Ws[k * 128 + tx * 8 + 4];
            unsigned long long d0 = dupf(a0.x), d1 = dupf(a0.y);
            unsigned long long d2 = dupf(a0.z), d3 = dupf(a0.w);
            unsigned long long d4 = dupf(a1.x), d5 = dupf(a1.y);
            unsigned long long d6 = dupf(a1.z), d7 = dupf(a1.w);
            FMA2(acc[0][0], d0, w0.x); FMA2(acc[0][1], d0, w0.y);
            FMA2(acc[0][2], d0, w1.x); FMA2(acc[0][3], d0, w1.y);
            FMA2(acc[1][0], d1, w0.x); FMA2(acc[1][1], d1, w0.y);
            FMA2(acc[1][2], d1, w1.x); FMA2(acc[1][3], d1, w1.y);
            FMA2(acc[2][0], d2, w0.x); FMA2(acc[2][1], d2, w0.y);
            FMA2(acc[2][2], d2, w1.x); FMA2(acc[2][3], d2, w1.y);
            FMA2(acc[3][0], d3, w0.x); FMA2(acc[3][1], d3, w0.y);
            FMA2(acc[3][2], d3, w1.x); FMA2(acc[3][3], d3, w1.y);
            FMA2(acc[4][0], d4, w0.x); FMA2(acc[4][1], d4, w0.y);
            FMA2(acc[4][2], d4, w1.x); FMA2(acc[4][3], d4, w1.y);
            FMA2(acc[5][0], d5, w0.x); FMA2(acc[5][1], d5, w0.y);
            FMA2(acc[5][2], d5, w1.x); FMA2(acc[5][3], d5, w1.y);
            FMA2(acc[6][0], d6, w0.x); FMA2(acc[6][1], d6, w0.y);
            FMA2(acc[6][2], d6, w1.x); FMA2(acc[6][3], d6, w1.y);
            FMA2(acc[7][0], d7, w0.x); FMA2(acc[7][1], d7, w0.y);
            FMA2(acc[7][2], d7, w1.x); FMA2(acc[7][3], d7, w1.y);
        }
        __syncthreads();
    }

    // Epilogue: unpack, add bias, store, accumulate LN stats
    float4 bo0 = __ldg((const float4*)(bias + tx * 8));
    float4 bo1 = __ldg((const float4*)(bias + tx * 8 + 4));
    float lsum = 0.f, lsq = 0.f;
    #pragma unroll
    for (int r = 0; r < 8; r++) {
        int grow = row0 + ty * 8 + r;
        if (grow < n) {
            float o[8];
            #pragma unroll
            for (int p = 0; p < 4; p++) {
                unsigned lo, hi;
                asm("mov.b64 {%0,%1}, %2;" : "=r"(lo), "=r"(hi) : "l"(acc[r][p]));
                o[2 * p]     = __uint_as_float(lo);
                o[2 * p + 1] = __uint_as_float(hi);
            }
            o[0] += bo0.x; o[1] += bo0.y; o[2] += bo0.z; o[3] += bo0.w;
            o[4] += bo1.x; o[5] += bo1.y; o[6] += bo1.z; o[7] += bo1.w;
            float4* yp = (float4*)(Y + (size_t)grow * D + tx * 8);
            yp[0] = make_float4(o[0], o[1], o[2], o[3]);
            yp[1] = make_float4(o[4], o[5], o[6], o[7]);
            #pragma unroll
            for (int q = 0; q < 8; q++) { lsum += o[q]; lsq += o[q] * o[q]; }
        }
    }
    #pragma unroll
    for (int off = 16; off; off >>= 1) {
        lsum += __shfl_xor_sync(0xffffffffu, lsum, off);
        lsq  += __shfl_xor_sync(0xffffffffu, lsq,  off);
    }
    int wid = tid >> 5, lane = tid & 31;
    __syncthreads();
    if (lane == 0) { red[wid] = lsum; red[8 + wid] = lsq; }
    __syncthreads();
    if (tid == 0) {
        float s = 0.f, q = 0.f;
        #pragma unroll
        for (int w = 0; w < 8; w++) { s += red[w]; q += red[8 + w]; }
        atomicAdd(acc_out,     (double)s);
        atomicAdd(acc_out + 1, (double)q);
    }
}

// ---------------------------------------------------------------------------
// Final: out = relu(LN(out)) in place (stats finalized in-block)
// ---------------------------------------------------------------------------
__global__ void k_final(float* __restrict__ y, const float* __restrict__ lnw,
                        const float* __restrict__ lnb, const double* __restrict__ acc_in,
                        double cnt, int n) {
    __shared__ float sm[2];
    if (threadIdx.x == 0) {
        double m = acc_in[0] / cnt;
        double var = acc_in[1] / cnt - m * m;
        if (var < 0.0) var = 0.0;
        sm[0] = (float)m;
        sm[1] = 1.0f / ((float)sqrt(var) + 1e-5f);
    }
    __syncthreads();
    int i = blockIdx.x * blockDim.x + threadIdx.x;
    if (i >= n * (D / 4)) return;
    float mean = sm[0], inv = sm[1];
    float4 v = ((float4*)y)[i];
    int kb = (i * 4) & (D - 1);
    float4 wv = __ldg((const float4*)(lnw + kb));
    float4 bv = __ldg((const float4*)(lnb + kb));
    v.x = fmaxf(fmaf((v.x - mean) * inv, wv.x, bv.x), 0.f);
    v.y = fmaxf(fmaf((v.y - mean) * inv, wv.y, bv.y), 0.f);
    v.z = fmaxf(fmaf((v.z - mean) * inv, wv.z, bv.z), 0.f);
    v.w = fmaxf(fmaf((v.w - mean) * inv, wv.w, bv.w), 0.f);
    ((float4*)y)[i] = v;
}

// ---------------------------------------------------------------------------
extern "C" void kernel_launch(void* const* d_in, const int* in_sizes, int n_in,
                              void* d_out, int out_size) {
    const float* node = (const float*)d_in[0];
    const int*   ei   = (const int*)d_in[1];
    const float* epsp = (const float*)d_in[4];
    const float* W1 = (const float*)d_in[5];  const float* b1 = (const float*)d_in[6];
    const float* l1w = (const float*)d_in[7]; const float* l1b = (const float*)d_in[8];
    const float* W2 = (const float*)d_in[9];  const float* b2 = (const float*)d_in[10];
    const float* l2w = (const float*)d_in[11]; const float* l2b = (const float*)d_in[12];
    const float* W3 = (const float*)d_in[13]; const float* b3 = (const float*)d_in[14];
    const float* low = (const float*)d_in[15]; const float* lob = (const float*)d_in[16];
    float* out = (float*)d_out;

    int n  = in_sizes[0] / D;
    int ne = in_sizes[1] / 2;

    float *hP, *y1P, *y2P; double* accP; int* degP;
    cudaGetSymbolAddress((void**)&hP,  g_h);
    cudaGetSymbolAddress((void**)&y1P, g_y1);
    cudaGetSymbolAddress((void**)&y2P, g_y2);
    cudaGetSymbolAddress((void**)&accP, g_acc);
    cudaGetSymbolAddress((void**)&degP, g_deg);

    cudaFuncSetAttribute(k_gemm<false>, cudaFuncAttributeMaxDynamicSharedMemorySize, SM_TOT);
    cudaFuncSetAttribute(k_gemm<true>,  cudaFuncAttributeMaxDynamicSharedMemorySize, SM_TOT);

    int t4 = n * (D / 4);
    double cnt = (double)n * D;
    int gb = (n + 127) / 128;

    // CSR build (counting sort by dst)
    cudaMemsetAsync(degP, 0, (size_t)(n + 1) * sizeof(int));
    k_hist<<<(ne / 4 + 255) / 256, 256>>>(ei + ne, ne);
    k_scan<<<1, 1024>>>(n + 1);
    k_fill<<<(ne / 4 + 255) / 256, 256>>>(ei, ne);

    // Aggregation (atomic-free) + fused (1+eps)*node
    k_aggr<<<(n * 32 + 255) / 256, 256>>>(node, epsp, n);

    // MLP with fused graph-LN stats
    k_gemm<false><<<gb, 256, SM_TOT>>>(hP,  W1, b1, nullptr, nullptr, nullptr,  cnt, y1P, accP,     n);
    k_gemm<true ><<<gb, 256, SM_TOT>>>(y1P, W2, b2, l1w, l1b, accP,             cnt, y2P, accP + 2, n);
    k_gemm<true ><<<gb, 256, SM_TOT>>>(y2P, W3, b3, l2w, l2b, accP + 2,         cnt, out, accP + 4, n);
    k_final<<<(t4 + 255) / 256, 256>>>(out, low, lob, accP + 4, cnt, n);
}